// round 2
// baseline (speedup 1.0000x reference)
#include <cuda_runtime.h>
#include <cuda_bf16.h>

// CL4CTR loss on GB300.
//   x:   [4096, 39] int32 field indices      (d_in[0])
//   emb: [3900000, 16] float32               (d_in[1])
//   out: scalar float32
//
// Structure:
//   cl4_zero  : zero global accumulators (graph-replayable)
//   cl4_main  : 512 blocks x 256 thr; one warp = one sample.
//               gather -> transposed smem tile xT[16][40] (row 39 zero pad)
//               norms, sum(sq), 4x4-register-tiled Gram over 55 triangle tiles,
//               per-pair reciprocal via bit-trick + 3 Newton (no MUFU),
//               block-level s[39][16] partial -> global atomics
//   cl4_final : 1 warp; sum(s^2), combine, write scalar.

#define F_FIELDS 39
#define FP 40            // padded rows
#define NGRP 10          // 4-row groups
#define WARPS 8
#define EPSV 1e-4f

__device__ float g_s[624];    // s[f][d], f<39, d<16
__device__ float g_acc[2];    // [0]=sum(sq), [1]=uniform sum

#define TT(i,j,w) ((unsigned)((i) | ((j)<<8) | ((w)<<16)))
__constant__ unsigned c_tiles[64] = {
  TT(0,0,1),TT(0,1,2),TT(0,2,2),TT(0,3,2),TT(0,4,2),TT(0,5,2),TT(0,6,2),TT(0,7,2),TT(0,8,2),TT(0,9,2),
  TT(1,1,1),TT(1,2,2),TT(1,3,2),TT(1,4,2),TT(1,5,2),TT(1,6,2),TT(1,7,2),TT(1,8,2),TT(1,9,2),
  TT(2,2,1),TT(2,3,2),TT(2,4,2),TT(2,5,2),TT(2,6,2),TT(2,7,2),TT(2,8,2),TT(2,9,2),
  TT(3,3,1),TT(3,4,2),TT(3,5,2),TT(3,6,2),TT(3,7,2),TT(3,8,2),TT(3,9,2),
  TT(4,4,1),TT(4,5,2),TT(4,6,2),TT(4,7,2),TT(4,8,2),TT(4,9,2),
  TT(5,5,1),TT(5,6,2),TT(5,7,2),TT(5,8,2),TT(5,9,2),
  TT(6,6,1),TT(6,7,2),TT(6,8,2),TT(6,9,2),
  TT(7,7,1),TT(7,8,2),TT(7,9,2),
  TT(8,8,1),TT(8,9,2),
  TT(9,9,1),
  TT(0,0,0),TT(0,0,0),TT(0,0,0),TT(0,0,0),TT(0,0,0),TT(0,0,0),TT(0,0,0),TT(0,0,0),TT(0,0,0)
};

// Reciprocal without MUFU: magic seed + 3 Newton steps (fma pipe only).
__device__ __forceinline__ float frcp_nt(float d) {
    float r = __int_as_float(0x7EF311C3 - __float_as_int(d));
    r = r * fmaf(-d, r, 2.0f);
    r = r * fmaf(-d, r, 2.0f);
    r = r * fmaf(-d, r, 2.0f);
    return r;
}

__global__ void __launch_bounds__(256) cl4_zero() {
    int t = blockIdx.x * blockDim.x + threadIdx.x;
    if (t < 624) g_s[t] = 0.0f;
    if (t < 2)   g_acc[t] = 0.0f;
}

__global__ void __launch_bounds__(256) cl4_main(const int* __restrict__ x,
                                                const float* __restrict__ emb) {
    __shared__ __align__(16) float s_xt[WARPS][16 * FP]; // transposed tile [k][r]
    __shared__ float s_n[WARPS][FP];
    __shared__ float s_red[WARPS][2];

    const int w    = threadIdx.x >> 5;
    const int lane = threadIdx.x & 31;
    const int b    = blockIdx.x * WARPS + w;     // 512*8 = 4096 samples exactly
    const int* xr  = x + b * F_FIELDS;

    // ---- gather: 39 rows x 4 float4 chunks = 156 loads, transpose into smem
    for (int i = lane; i < 156; i += 32) {
        int r = i >> 2, c = i & 3;
        int row = __ldg(&xr[r]) + r * 100000;
        float4 v = *reinterpret_cast<const float4*>(emb + (size_t)row * 16 + c * 4);
        float* dst = &s_xt[w][c * 4 * FP + r];
        dst[0]      = v.x;
        dst[FP]     = v.y;
        dst[2 * FP] = v.z;
        dst[3 * FP] = v.w;
    }
    if (lane < 16) s_xt[w][lane * FP + 39] = 0.0f;   // zero pad row
    __syncwarp();

    // ---- per-row squared norms + sum(sq)
    float sumsq = 0.0f;
    for (int rr = lane; rr < FP; rr += 32) {
        float sq = 0.0f;
        #pragma unroll
        for (int k = 0; k < 16; k++) {
            float v = s_xt[w][k * FP + rr];
            sq = fmaf(v, v, sq);
        }
        s_n[w][rr] = sqrtf(sq);
        sumsq += sq;                                  // pad row adds 0
    }
    __syncwarp();

    // ---- 4x4-register-tiled Gram over the group triangle (55 tiles + 9 pads)
    const float4* xt4 = reinterpret_cast<const float4*>(s_xt[w]);  // [16][10]
    float usum = 0.0f;

    #pragma unroll
    for (int rep = 0; rep < 2; rep++) {
        unsigned e = c_tiles[rep * 32 + lane];
        int I = e & 255, J = (e >> 8) & 255;
        float wgt = (float)(e >> 16);

        float acc[4][4];
        #pragma unroll
        for (int i = 0; i < 4; i++)
            #pragma unroll
            for (int j = 0; j < 4; j++) acc[i][j] = 0.0f;

        #pragma unroll
        for (int k = 0; k < 16; k++) {
            float4 a  = xt4[k * NGRP + I];
            float4 bb = xt4[k * NGRP + J];
            float af[4] = {a.x, a.y, a.z, a.w};
            float bf[4] = {bb.x, bb.y, bb.z, bb.w};
            #pragma unroll
            for (int i = 0; i < 4; i++)
                #pragma unroll
                for (int j = 0; j < 4; j++)
                    acc[i][j] = fmaf(af[i], bf[j], acc[i][j]);
        }

        float nf[4], ng[4];
        #pragma unroll
        for (int i = 0; i < 4; i++) {
            nf[i] = s_n[w][4 * I + i];
            ng[i] = s_n[w][4 * J + i];
        }

        float ts = 0.0f;
        #pragma unroll
        for (int i = 0; i < 4; i++)
            #pragma unroll
            for (int j = 0; j < 4; j++) {
                float den = fmaf(nf[i], ng[j], EPSV);
                ts = fmaf(acc[i][j], frcp_nt(den), ts);
            }
        usum = fmaf(wgt, ts, usum);
    }

    // ---- warp reductions
    #pragma unroll
    for (int o = 16; o; o >>= 1) {
        usum  += __shfl_xor_sync(0xffffffffu, usum, o);
        sumsq += __shfl_xor_sync(0xffffffffu, sumsq, o);
    }
    if (lane == 0) { s_red[w][0] = sumsq; s_red[w][1] = usum; }
    __syncthreads();

    // ---- block-level s[39][16] partial + scalar partials -> global
    for (int e = threadIdx.x; e < 624; e += 256) {
        int f = e >> 4, k = e & 15;
        float v = 0.0f;
        #pragma unroll
        for (int ww = 0; ww < WARPS; ww++) v += s_xt[ww][k * FP + f];
        atomicAdd(&g_s[e], v);
    }
    if (threadIdx.x == 0) {
        float a = 0.0f, u = 0.0f;
        #pragma unroll
        for (int ww = 0; ww < WARPS; ww++) { a += s_red[ww][0]; u += s_red[ww][1]; }
        atomicAdd(&g_acc[0], a);
        atomicAdd(&g_acc[1], u);
    }
}

__global__ void __launch_bounds__(32) cl4_final(float* __restrict__ out) {
    int lane = threadIdx.x;
    float ssq = 0.0f;
    for (int e = lane; e < 624; e += 32) {
        float v = g_s[e];
        ssq = fmaf(v, v, ssq);
    }
    #pragma unroll
    for (int o = 16; o; o >>= 1) ssq += __shfl_xor_sync(0xffffffffu, ssq, o);

    if (lane == 0) {
        double sumsq = (double)g_acc[0];
        double usum  = (double)g_acc[1];
        double pair  = 4096.0 * sumsq - (double)ssq;
        double align = pair / (8386560.0 * 39.0);          // n_pairs * F
        double uni   = usum / (4096.0 * 39.0 * 39.0);      // B * F * F
        out[0] = (float)((align + uni) * 0.01);            // * BETA
    }
}

extern "C" void kernel_launch(void* const* d_in, const int* in_sizes, int n_in,
                              void* d_out, int out_size) {
    const int*   x   = (const int*)d_in[0];
    const float* emb = (const float*)d_in[1];
    cl4_zero<<<3, 256>>>();
    cl4_main<<<512, 256>>>(x, emb);
    cl4_final<<<1, 32>>>((float*)d_out);
}

// round 4
// speedup vs baseline: 1.0960x; 1.0960x over previous
#include <cuda_runtime.h>
#include <cuda_bf16.h>

// CL4CTR loss on GB300 — single fused kernel.
//   x:   [4096, 39] int32 field indices      (d_in[0])
//   emb: [3900000, 16] float32               (d_in[1])
//   out: scalar float32
//
// One kernel, 512 blocks x 256 threads; 1 warp = 1 sample.
//   gather -> transposed smem tile xT[16][40]; norms; 4x4-register-tiled Gram
//   over 55 triangle tiles; bit-trick + 2-Newton reciprocal (no MUFU);
//   block partials -> global atomics; the LAST block (atomic counter) reduces
//   s^2, combines, writes the scalar, and RE-ZEROES all accumulators so every
//   graph replay starts from the zero-invariant (device globals are
//   zero-initialized at module load).

#define F_FIELDS 39
#define FP 40            // padded rows
#define NGRP 10          // 4-row groups
#define WARPS 8
#define NBLOCKS 512
#define EPSV 1e-4f

__device__ float g_s[624];       // s[f][d]
__device__ float g_acc[2];       // [0]=sum(sq), [1]=uniform sum
__device__ unsigned g_count;     // arrival counter (returns to 0 each run)

#define TT(i,j,w) ((unsigned)((i) | ((j)<<8) | ((w)<<16)))
__constant__ unsigned c_tiles[64] = {
  TT(0,0,1),TT(0,1,2),TT(0,2,2),TT(0,3,2),TT(0,4,2),TT(0,5,2),TT(0,6,2),TT(0,7,2),TT(0,8,2),TT(0,9,2),
  TT(1,1,1),TT(1,2,2),TT(1,3,2),TT(1,4,2),TT(1,5,2),TT(1,6,2),TT(1,7,2),TT(1,8,2),TT(1,9,2),
  TT(2,2,1),TT(2,3,2),TT(2,4,2),TT(2,5,2),TT(2,6,2),TT(2,7,2),TT(2,8,2),TT(2,9,2),
  TT(3,3,1),TT(3,4,2),TT(3,5,2),TT(3,6,2),TT(3,7,2),TT(3,8,2),TT(3,9,2),
  TT(4,4,1),TT(4,5,2),TT(4,6,2),TT(4,7,2),TT(4,8,2),TT(4,9,2),
  TT(5,5,1),TT(5,6,2),TT(5,7,2),TT(5,8,2),TT(5,9,2),
  TT(6,6,1),TT(6,7,2),TT(6,8,2),TT(6,9,2),
  TT(7,7,1),TT(7,8,2),TT(7,9,2),
  TT(8,8,1),TT(8,9,2),
  TT(9,9,1),
  TT(0,0,0),TT(0,0,0),TT(0,0,0),TT(0,0,0),TT(0,0,0),TT(0,0,0),TT(0,0,0),TT(0,0,0),TT(0,0,0)
};

// Reciprocal without MUFU: magic seed + 2 Newton steps (max rel err ~6e-6).
__device__ __forceinline__ float frcp_nt(float d) {
    float r = __int_as_float(0x7EF311C3 - __float_as_int(d));
    r = r * fmaf(-d, r, 2.0f);
    r = r * fmaf(-d, r, 2.0f);
    return r;
}

__global__ void __launch_bounds__(256) cl4_fused(const int* __restrict__ x,
                                                 const float* __restrict__ emb,
                                                 float* __restrict__ out) {
    __shared__ __align__(16) float s_xt[WARPS][16 * FP]; // transposed tile [k][r]
    __shared__ float s_n[WARPS][FP];
    __shared__ float s_red[WARPS][2];
    __shared__ int   s_idx[WARPS][40];
    __shared__ unsigned s_last;
    __shared__ float s_fin[8];

    const int w    = threadIdx.x >> 5;
    const int lane = threadIdx.x & 31;
    const int b    = blockIdx.x * WARPS + w;     // 512*8 = 4096 samples exactly
    const int* xr  = x + b * F_FIELDS;

    // ---- prefetch indices (2 coalesced loads), add per-field offsets
    if (lane < 39) s_idx[w][lane] = __ldg(&xr[lane]) + lane * 100000;
    {
        int l2 = lane + 32;
        if (l2 < 39) s_idx[w][l2] = __ldg(&xr[l2]) + l2 * 100000;
    }
    __syncwarp();

    // ---- gather: 39 rows x 4 float4 chunks = 156 loads, transpose into smem.
    // All 5 LDGs per lane issue back-to-back (only an LDS in front).
    #pragma unroll
    for (int it = 0; it < 5; it++) {
        int i = it * 32 + lane;
        if (i < 156) {
            int r = i >> 2, c = i & 3;
            int row = s_idx[w][r];
            float4 v = *reinterpret_cast<const float4*>(emb + (size_t)row * 16 + c * 4);
            float* dst = &s_xt[w][c * 4 * FP + r];
            dst[0]      = v.x;
            dst[FP]     = v.y;
            dst[2 * FP] = v.z;
            dst[3 * FP] = v.w;
        }
    }
    if (lane < 16) s_xt[w][lane * FP + 39] = 0.0f;   // zero pad row
    __syncwarp();

    // ---- per-row squared norms + sum(sq)
    float sumsq = 0.0f;
    for (int rr = lane; rr < FP; rr += 32) {
        float sq = 0.0f;
        #pragma unroll
        for (int k = 0; k < 16; k++) {
            float v = s_xt[w][k * FP + rr];
            sq = fmaf(v, v, sq);
        }
        s_n[w][rr] = sqrtf(sq);
        sumsq += sq;                                  // pad row adds 0
    }
    __syncwarp();

    // ---- 4x4-register-tiled Gram over the group triangle (55 tiles + 9 pads)
    const float4* xt4 = reinterpret_cast<const float4*>(s_xt[w]);  // [16][10]
    float usum = 0.0f;

    #pragma unroll
    for (int rep = 0; rep < 2; rep++) {
        unsigned e = c_tiles[rep * 32 + lane];
        int I = e & 255, J = (e >> 8) & 255;
        float wgt = (float)(e >> 16);

        float acc[4][4];
        #pragma unroll
        for (int i = 0; i < 4; i++)
            #pragma unroll
            for (int j = 0; j < 4; j++) acc[i][j] = 0.0f;

        #pragma unroll
        for (int k = 0; k < 16; k++) {
            float4 a  = xt4[k * NGRP + I];
            float4 bb = xt4[k * NGRP + J];
            float af[4] = {a.x, a.y, a.z, a.w};
            float bf[4] = {bb.x, bb.y, bb.z, bb.w};
            #pragma unroll
            for (int i = 0; i < 4; i++)
                #pragma unroll
                for (int j = 0; j < 4; j++)
                    acc[i][j] = fmaf(af[i], bf[j], acc[i][j]);
        }

        float nf[4], ng[4];
        #pragma unroll
        for (int i = 0; i < 4; i++) {
            nf[i] = s_n[w][4 * I + i];
            ng[i] = s_n[w][4 * J + i];
        }

        float ts = 0.0f;
        #pragma unroll
        for (int i = 0; i < 4; i++)
            #pragma unroll
            for (int j = 0; j < 4; j++) {
                float den = fmaf(nf[i], ng[j], EPSV);
                ts = fmaf(acc[i][j], frcp_nt(den), ts);
            }
        usum = fmaf(wgt, ts, usum);
    }

    // ---- warp reductions
    #pragma unroll
    for (int o = 16; o; o >>= 1) {
        usum  += __shfl_xor_sync(0xffffffffu, usum, o);
        sumsq += __shfl_xor_sync(0xffffffffu, sumsq, o);
    }
    if (lane == 0) { s_red[w][0] = sumsq; s_red[w][1] = usum; }
    __syncthreads();

    // ---- block-level s[39][16] partial + scalar partials -> global atomics
    for (int e = threadIdx.x; e < 624; e += 256) {
        int f = e >> 4, k = e & 15;
        float v = 0.0f;
        #pragma unroll
        for (int ww = 0; ww < WARPS; ww++) v += s_xt[ww][k * FP + f];
        atomicAdd(&g_s[e], v);
    }
    if (threadIdx.x == 0) {
        float a = 0.0f, u = 0.0f;
        #pragma unroll
        for (int ww = 0; ww < WARPS; ww++) { a += s_red[ww][0]; u += s_red[ww][1]; }
        atomicAdd(&g_acc[0], a);
        atomicAdd(&g_acc[1], u);
    }

    // ---- last-block election
    __threadfence();
    __syncthreads();
    if (threadIdx.x == 0) s_last = atomicAdd(&g_count, 1u);
    __syncthreads();
    if (s_last != NBLOCKS - 1) return;

    // ---- final: sum(s^2), combine, write scalar, RE-ZERO accumulators
    float ssq = 0.0f;
    for (int e = threadIdx.x; e < 624; e += 256) {
        float v = g_s[e];
        ssq = fmaf(v, v, ssq);
        g_s[e] = 0.0f;                                // restore zero-invariant
    }
    #pragma unroll
    for (int o = 16; o; o >>= 1) ssq += __shfl_xor_sync(0xffffffffu, ssq, o);
    if (lane == 0) s_fin[w] = ssq;
    __syncthreads();

    if (threadIdx.x == 0) {
        float st = 0.0f;
        #pragma unroll
        for (int ww = 0; ww < WARPS; ww++) st += s_fin[ww];
        double sumsq_t = (double)g_acc[0];
        double usum_t  = (double)g_acc[1];
        double pair    = 4096.0 * sumsq_t - (double)st;
        double align   = pair / (8386560.0 * 39.0);        // n_pairs * F
        double uni     = usum_t / (4096.0 * 39.0 * 39.0);  // B * F * F
        out[0] = (float)((align + uni) * 0.01);            // * BETA
        g_acc[0] = 0.0f;
        g_acc[1] = 0.0f;
        g_count  = 0u;                                     // reset for next replay
    }
}

extern "C" void kernel_launch(void* const* d_in, const int* in_sizes, int n_in,
                              void* d_out, int out_size) {
    const int*   x   = (const int*)d_in[0];
    const float* emb = (const float*)d_in[1];
    cl4_fused<<<NBLOCKS, 256>>>(x, emb, (float*)d_out);
}